// round 16
// baseline (speedup 1.0000x reference)
#include <cuda_runtime.h>
#include <cuda_bf16.h>
#include <cuda_fp16.h>
#include <cstdint>

#define MAX_NODES 100000
#define MAX_EDGES 600000
#define D 128
#define TILE_M 128
#define GEMM_THREADS 256
#define LDA 136                    // padded row stride (elements) -> 272B, LDSM conflict-free

// ---------------------------------------------------------------------------
// Device scratch (no cudaMalloc allowed)
// ---------------------------------------------------------------------------
__device__ int    g_total;
__device__ int2   g_epack[MAX_EDGES];             // CSR: {src, dinv[src] bits}
__device__ int    g_cnt[MAX_NODES];               // in-degree; re-zeroed by k_offsets
__device__ int    g_off[MAX_NODES];               // CSR range starts (disjoint)
__device__ int    g_cursor[MAX_NODES];            // fill cursors (end = off+cnt)
__device__ float  g_dinv[MAX_NODES];              // rsqrt(deg+1)
__device__ __half g_yh[(size_t)MAX_NODES * D];    // y = x @ W (UNscaled, fp16)
__device__ uint4  g_Whi4[2048];                   // W hi plane, bf16 [k][n]
__device__ uint4  g_Wlo4[2048];                   // W lo plane, bf16 [k][n]

// ---------------------------------------------------------------------------
// PTX helpers: ldmatrix + bf16 mma.sync (plain sm_103-safe, no tcgen05)
// ---------------------------------------------------------------------------
__device__ __forceinline__ uint32_t smem_u32(const void* p) {
    uint32_t a;
    asm("{ .reg .u64 t; cvta.to.shared.u64 t, %1; cvt.u32.u64 %0, t; }"
        : "=r"(a) : "l"(p));
    return a;
}

__device__ __forceinline__ void ldsm_x4(uint32_t& r0, uint32_t& r1,
                                        uint32_t& r2, uint32_t& r3,
                                        uint32_t addr) {
    asm volatile("ldmatrix.sync.aligned.m8n8.x4.shared.b16 {%0,%1,%2,%3}, [%4];"
                 : "=r"(r0), "=r"(r1), "=r"(r2), "=r"(r3) : "r"(addr));
}

__device__ __forceinline__ void ldsm_x2_trans(uint32_t& r0, uint32_t& r1,
                                              uint32_t addr) {
    asm volatile("ldmatrix.sync.aligned.m8n8.x2.trans.shared.b16 {%0,%1}, [%2];"
                 : "=r"(r0), "=r"(r1) : "r"(addr));
}

__device__ __forceinline__ void mma_bf16(float* c, const uint32_t* a,
                                         const uint32_t* b) {
    asm volatile(
        "mma.sync.aligned.m16n8k16.row.col.f32.bf16.bf16.f32 "
        "{%0,%1,%2,%3}, {%4,%5,%6,%7}, {%8,%9}, {%0,%1,%2,%3};"
        : "+f"(c[0]), "+f"(c[1]), "+f"(c[2]), "+f"(c[3])
        : "r"(a[0]), "r"(a[1]), "r"(a[2]), "r"(a[3]), "r"(b[0]), "r"(b[1]));
}

// ---------------------------------------------------------------------------
// In-degree histogram straight off the input buffer (dst half only).
// Dtype detected per block (warp 0 ballots the first 64 words: int64 values
// < 1e5 have all-zero odd words). g_cnt is 0 on entry (BSS init first call,
// k_offsets re-zeroes it every replay).
// ---------------------------------------------------------------------------
__global__ void k_hist(const void* __restrict__ ei, int e, int n) {
    __shared__ int s_is64;
    if (threadIdx.x < 32) {
        int v = ((const int*)ei)[1 + 2 * threadIdx.x];
        unsigned nz = __ballot_sync(0xFFFFFFFFu, v != 0);
        if (threadIdx.x == 0) s_is64 = (nz == 0) ? 1 : 0;
    }
    __syncthreads();
    int i = blockIdx.x * blockDim.x + threadIdx.x;
    if (i == 0) g_total = 0;                     // seed for k_offsets
    if (i >= e) return;
    int d = s_is64 ? (int)((const long long*)ei)[e + i]
                   : ((const int*)ei)[e + i];
    if ((unsigned)d < (unsigned)n) atomicAdd(&g_cnt[d], 1);
}

// ---------------------------------------------------------------------------
// One-kernel CSR offsets: block-local scan + atomic block base. Also emits
// dinv = rsqrt(deg+1) and restores g_cnt to 0 for the next replay.
// ---------------------------------------------------------------------------
__global__ void k_offsets(int n) {
    __shared__ int sh[256];
    __shared__ int base;
    int i = blockIdx.x * 256 + threadIdx.x;
    int v = (i < n) ? g_cnt[i] : 0;
    sh[threadIdx.x] = v;
    __syncthreads();
    #pragma unroll
    for (int off = 1; off < 256; off <<= 1) {
        int t = (threadIdx.x >= off) ? sh[threadIdx.x - off] : 0;
        __syncthreads();
        sh[threadIdx.x] += t;
        __syncthreads();
    }
    if (threadIdx.x == 255) base = atomicAdd(&g_total, sh[255]);
    __syncthreads();
    if (i < n) {
        int o = base + sh[threadIdx.x] - v;   // exclusive within block + base
        g_off[i] = o;
        g_cursor[i] = o;
        g_dinv[i] = rsqrtf((float)v + 1.0f);
        g_cnt[i] = 0;                         // restore for next replay
    }
}

// Fill CSR straight off the input buffer: g_epack[pos] = {src, dinv[src]},
// grouped by dst. The random dinv[src] lookup happens HERE (hidden under the
// GEMM stream) instead of inside the critical-path gather loop.
__global__ void k_fill(const void* __restrict__ ei, int e, int n) {
    __shared__ int s_is64;
    if (threadIdx.x < 32) {
        int v = ((const int*)ei)[1 + 2 * threadIdx.x];
        unsigned nz = __ballot_sync(0xFFFFFFFFu, v != 0);
        if (threadIdx.x == 0) s_is64 = (nz == 0) ? 1 : 0;
    }
    __syncthreads();
    int i = blockIdx.x * blockDim.x + threadIdx.x;
    if (i >= e) return;
    int s, d;
    if (s_is64) {
        const long long* p = (const long long*)ei;
        s = (int)p[i];
        d = (int)p[e + i];
    } else {
        const int* p = (const int*)ei;
        s = p[i];
        d = p[e + i];
    }
    if ((unsigned)d >= (unsigned)n) return;
    if ((unsigned)s >= (unsigned)n) s = 0;
    int pos = atomicAdd(&g_cursor[d], 1);
    g_epack[pos] = make_int2(s, __float_as_int(g_dinv[s]));
}

// ---------------------------------------------------------------------------
// One-time W split: W[k][n] fp32 -> bf16 hi/lo planes (row-major [k][n]).
// ---------------------------------------------------------------------------
__global__ void k_wsplit(const float* __restrict__ W) {
    int i = blockIdx.x * blockDim.x + threadIdx.x;   // < 16384
    float v = W[i];
    __nv_bfloat16 h = __float2bfloat16(v);
    __nv_bfloat16 l = __float2bfloat16(v - __bfloat162float(h));
    ((__nv_bfloat16*)g_Whi4)[i] = h;
    ((__nv_bfloat16*)g_Wlo4)[i] = l;
}

// ---------------------------------------------------------------------------
// HMMA GEMM: y = x @ W (UNscaled) via bf16 hi/lo 3-term split; fp32 accum,
// result stored as fp16 (halves gather traffic; |y|~O(1) so fp16 is safe).
// Independent of the edge pipeline -> runs on a parallel stream.
// ---------------------------------------------------------------------------
#define SM_A_HI 0
#define SM_A_LO (SM_A_HI + 128 * LDA * 2)   // 34816
#define SM_B_HI (SM_A_LO + 128 * LDA * 2)
#define SM_B_LO (SM_B_HI + 128 * LDA * 2)
#define SMEM_TOTAL (SM_B_LO + 128 * LDA * 2)  // 139264

__global__ void __launch_bounds__(GEMM_THREADS, 1)
k_gemm_mma(const float* __restrict__ x, int n) {
    extern __shared__ __align__(16) char smem[];
    const uint32_t smem_base = smem_u32(smem);
    const int tid  = threadIdx.x;
    const int w    = tid >> 5;
    const int lane = tid & 31;
    const int row0 = blockIdx.x * TILE_M;

    // --- Copy precomputed W planes into padded SMEM (uint4 = 8 bf16) ---
    #pragma unroll 4
    for (int i = tid; i < 2048; i += GEMM_THREADS) {
        int r  = i >> 4;
        int c8 = (i & 15) * 8;
        size_t o = (size_t)(r * LDA + c8) * 2;
        *(uint4*)(smem + SM_B_HI + o) = g_Whi4[i];
        *(uint4*)(smem + SM_B_LO + o) = g_Wlo4[i];
    }

    // --- Convert x tile -> As_hi/As_lo (row-major [m][k], padded) ---
    #pragma unroll 4
    for (int i = tid; i < 128 * 32; i += GEMM_THREADS) {
        int r  = i >> 5;
        int c4 = (i & 31) * 4;
        int row = row0 + r;
        if (row >= n) row = n - 1;
        float4 v = *(const float4*)&x[(size_t)row * D + c4];
        __nv_bfloat16 hx = __float2bfloat16(v.x), hy = __float2bfloat16(v.y);
        __nv_bfloat16 hz = __float2bfloat16(v.z), hw = __float2bfloat16(v.w);
        __nv_bfloat16 lx = __float2bfloat16(v.x - __bfloat162float(hx));
        __nv_bfloat16 ly = __float2bfloat16(v.y - __bfloat162float(hy));
        __nv_bfloat16 lz = __float2bfloat16(v.z - __bfloat162float(hz));
        __nv_bfloat16 lw = __float2bfloat16(v.w - __bfloat162float(hw));
        size_t o = (size_t)(r * LDA + c4) * 2;
        *(__nv_bfloat162*)(smem + SM_A_HI + o)     = __nv_bfloat162(hx, hy);
        *(__nv_bfloat162*)(smem + SM_A_HI + o + 4) = __nv_bfloat162(hz, hw);
        *(__nv_bfloat162*)(smem + SM_A_LO + o)     = __nv_bfloat162(lx, ly);
        *(__nv_bfloat162*)(smem + SM_A_LO + o + 4) = __nv_bfloat162(lz, lw);
    }
    __syncthreads();

    float acc[16][4];
    #pragma unroll
    for (int t = 0; t < 16; t++)
        acc[t][0] = acc[t][1] = acc[t][2] = acc[t][3] = 0.0f;

    const int m0 = w * 16;
    const int amat = lane >> 3;
    const int arow = m0 + ((amat & 1) * 8) + (lane & 7);
    const int acol8 = (amat >> 1) * 8;
    const int bmat = (lane >> 3) & 1;
    const int brow_base = bmat * 8 + (lane & 7);

    #pragma unroll
    for (int ks = 0; ks < 8; ks++) {
        uint32_t a_hi[4], a_lo[4];
        uint32_t a_addr = smem_base + SM_A_HI +
                          (uint32_t)(arow * LDA + ks * 16 + acol8) * 2;
        ldsm_x4(a_hi[0], a_hi[1], a_hi[2], a_hi[3], a_addr);
        ldsm_x4(a_lo[0], a_lo[1], a_lo[2], a_lo[3],
                a_addr + (SM_A_LO - SM_A_HI));

        uint32_t b_base = smem_base + SM_B_HI +
                          (uint32_t)((ks * 16 + brow_base) * LDA) * 2;
        #pragma unroll
        for (int nt = 0; nt < 16; nt++) {
            uint32_t b_hi[2], b_lo[2];
            uint32_t b_addr = b_base + nt * 16;
            ldsm_x2_trans(b_hi[0], b_hi[1], b_addr);
            ldsm_x2_trans(b_lo[0], b_lo[1], b_addr + (SM_B_LO - SM_B_HI));
            mma_bf16(acc[nt], a_hi, b_hi);
            mma_bf16(acc[nt], a_hi, b_lo);
            mma_bf16(acc[nt], a_lo, b_hi);
        }
    }

    // --- Epilogue: write raw y as fp16 (no scaling — dinv applied in gather) ---
    const int r_lo  = lane >> 2;
    const int cpair = (lane & 3) * 2;
    const int row_a = row0 + m0 + r_lo;
    const int row_b = row_a + 8;

    #pragma unroll
    for (int nt = 0; nt < 16; nt++) {
        int col = nt * 8 + cpair;
        if (row_a < n) {
            *(__half2*)&g_yh[(size_t)row_a * D + col] =
                __floats2half2_rn(acc[nt][0], acc[nt][1]);
        }
        if (row_b < n) {
            *(__half2*)&g_yh[(size_t)row_b * D + col] =
                __floats2half2_rn(acc[nt][2], acc[nt][3]);
        }
    }
}

// ---------------------------------------------------------------------------
// Gather (round-11 loop structure, fp16 rows): one warp per destination.
// Lanes batch-load up to 32 {src, dinv} pairs (coalesced int2), shfl both
// from registers — the inner loop's ONLY memory dependence is the y-row load.
// out[d] = dd*(dd*y[d] + sum dinv[s]*y[s]) + b.
// ---------------------------------------------------------------------------
__global__ void __launch_bounds__(256) k_gather(const float* __restrict__ b,
                                                float* __restrict__ out,
                                                int n) {
    int d = (blockIdx.x * 256 + threadIdx.x) >> 5;
    if (d >= n) return;
    int lane = threadIdx.x & 31;
    const __half* __restrict__ y = g_yh;

    int beg = g_off[d];
    int cnt = g_cursor[d] - beg;     // filled count
    float dd = g_dinv[d];

    uint2 uself = *(const uint2*)(y + (size_t)d * D + lane * 4);
    float2 s0 = __half22float2(*(__half2*)&uself.x);
    float2 s1 = __half22float2(*(__half2*)&uself.y);
    float4 acc;                      // self-loop term: dd * y[d]
    acc.x = dd * s0.x; acc.y = dd * s0.y; acc.z = dd * s1.x; acc.w = dd * s1.y;

    int k = 0;
    while (k < cnt) {
        int m = cnt - k;
        if (m > 32) m = 32;
        int sid = 0; float sdv = 0.0f;
        if (lane < m) {
            int2 pk = g_epack[beg + k + lane];
            sid = pk.x;
            sdv = __int_as_float(pk.y);
        }
        for (int j = 0; j < m; j++) {
            int   sj = __shfl_sync(0xFFFFFFFFu, sid, j);
            float ds = __shfl_sync(0xFFFFFFFFu, sdv, j);
            uint2 u = *(const uint2*)(y + (size_t)sj * D + lane * 4);
            float2 f0 = __half22float2(*(__half2*)&u.x);
            float2 f1 = __half22float2(*(__half2*)&u.y);
            acc.x = fmaf(ds, f0.x, acc.x);
            acc.y = fmaf(ds, f0.y, acc.y);
            acc.z = fmaf(ds, f1.x, acc.z);
            acc.w = fmaf(ds, f1.y, acc.w);
        }
        k += m;
    }

    float4 bb = *(const float4*)&b[lane * 4];
    float4 r;
    r.x = fmaf(acc.x, dd, bb.x);
    r.y = fmaf(acc.y, dd, bb.y);
    r.z = fmaf(acc.z, dd, bb.z);
    r.w = fmaf(acc.w, dd, bb.w);
    *(float4*)&out[(size_t)d * D + lane * 4] = r;
}

// ---------------------------------------------------------------------------
extern "C" void kernel_launch(void* const* d_in, const int* in_sizes, int n_in,
                              void* d_out, int out_size) {
    const float* x  = (const float*)d_in[0];
    const void*  ei = (const void*)d_in[1];
    const float* W  = (const float*)d_in[2];
    const float* b  = (const float*)d_in[3];
    float* out = (float*)d_out;

    int n = in_sizes[0] / D;   // 100000
    int e = in_sizes[1] / 2;   // 600000
    int nb = (n + 255) / 256;  // 391

    // Fork the GEMM pipeline (wsplit -> gemm, depends only on x/W) onto a
    // side stream so it overlaps the edge pipeline; join before the gather.
    cudaStream_t s2;
    cudaStreamCreateWithFlags(&s2, cudaStreamNonBlocking);
    cudaEvent_t e_fork, e_gemm;
    cudaEventCreateWithFlags(&e_fork, cudaEventDisableTiming);
    cudaEventCreateWithFlags(&e_gemm, cudaEventDisableTiming);

    cudaEventRecord(e_fork, 0);
    cudaStreamWaitEvent(s2, e_fork, 0);

    // Stream B: GEMM pipeline
    k_wsplit<<<64, 256, 0, s2>>>(W);
    cudaFuncSetAttribute(k_gemm_mma, cudaFuncAttributeMaxDynamicSharedMemorySize,
                         SMEM_TOTAL);
    k_gemm_mma<<<(n + TILE_M - 1) / TILE_M, GEMM_THREADS, SMEM_TOTAL, s2>>>(x, n);
    cudaEventRecord(e_gemm, s2);

    // Stream A (capture stream): edge pipeline
    k_hist<<<(e + 255) / 256, 256>>>(ei, e, n);
    k_offsets<<<nb, 256>>>(n);
    k_fill<<<(e + 255) / 256, 256>>>(ei, e, n);

    // Join and gather
    cudaStreamWaitEvent(0, e_gemm, 0);
    k_gather<<<(n * 32 + 255) / 256, 256>>>(b, out, n);
}

// round 17
// speedup vs baseline: 1.1162x; 1.1162x over previous
#include <cuda_runtime.h>
#include <cuda_bf16.h>
#include <cuda_fp16.h>
#include <cstdint>

#define MAX_NODES 100000
#define MAX_EDGES 600000
#define D 128
#define TILE_M 64                  // 64-row tiles -> 104 KB smem -> 2 CTAs/SM
#define GEMM_THREADS 256
#define LDA 136                    // padded row stride (elements) -> 272B, LDSM conflict-free

// ---------------------------------------------------------------------------
// Device scratch (no cudaMalloc allowed)
// ---------------------------------------------------------------------------
__device__ int    g_total;
__device__ int    g_esrc[MAX_EDGES];              // CSR col indices (src per dst)
__device__ int    g_cnt[MAX_NODES];               // in-degree; re-zeroed by k_offsets
__device__ int    g_off[MAX_NODES];               // CSR range starts (disjoint)
__device__ int    g_cursor[MAX_NODES];            // fill cursors (end = off+cnt)
__device__ float  g_dinv[MAX_NODES];              // rsqrt(deg+1)
__device__ __half g_yh[(size_t)MAX_NODES * D];    // y = x @ W (UNscaled, fp16)
__device__ uint4  g_Whi4[2048];                   // W hi plane, bf16 [k][n]
__device__ uint4  g_Wlo4[2048];                   // W lo plane, bf16 [k][n]

// ---------------------------------------------------------------------------
// PTX helpers: ldmatrix + bf16 mma.sync (plain sm_103-safe, no tcgen05)
// ---------------------------------------------------------------------------
__device__ __forceinline__ uint32_t smem_u32(const void* p) {
    uint32_t a;
    asm("{ .reg .u64 t; cvta.to.shared.u64 t, %1; cvt.u32.u64 %0, t; }"
        : "=r"(a) : "l"(p));
    return a;
}

__device__ __forceinline__ void ldsm_x4(uint32_t& r0, uint32_t& r1,
                                        uint32_t& r2, uint32_t& r3,
                                        uint32_t addr) {
    asm volatile("ldmatrix.sync.aligned.m8n8.x4.shared.b16 {%0,%1,%2,%3}, [%4];"
                 : "=r"(r0), "=r"(r1), "=r"(r2), "=r"(r3) : "r"(addr));
}

__device__ __forceinline__ void ldsm_x2_trans(uint32_t& r0, uint32_t& r1,
                                              uint32_t addr) {
    asm volatile("ldmatrix.sync.aligned.m8n8.x2.trans.shared.b16 {%0,%1}, [%2];"
                 : "=r"(r0), "=r"(r1) : "r"(addr));
}

__device__ __forceinline__ void mma_bf16(float* c, const uint32_t* a,
                                         const uint32_t* b) {
    asm volatile(
        "mma.sync.aligned.m16n8k16.row.col.f32.bf16.bf16.f32 "
        "{%0,%1,%2,%3}, {%4,%5,%6,%7}, {%8,%9}, {%0,%1,%2,%3};"
        : "+f"(c[0]), "+f"(c[1]), "+f"(c[2]), "+f"(c[3])
        : "r"(a[0]), "r"(a[1]), "r"(a[2]), "r"(a[3]), "r"(b[0]), "r"(b[1]));
}

// ---------------------------------------------------------------------------
// In-degree histogram straight off the input buffer (dst half only).
// Dtype detected per block (warp 0 ballots the first 64 words: int64 values
// < 1e5 have all-zero odd words). g_cnt is 0 on entry (BSS init first call,
// k_offsets re-zeroes it every replay).
// ---------------------------------------------------------------------------
__global__ void k_hist(const void* __restrict__ ei, int e, int n) {
    __shared__ int s_is64;
    if (threadIdx.x < 32) {
        int v = ((const int*)ei)[1 + 2 * threadIdx.x];
        unsigned nz = __ballot_sync(0xFFFFFFFFu, v != 0);
        if (threadIdx.x == 0) s_is64 = (nz == 0) ? 1 : 0;
    }
    __syncthreads();
    int i = blockIdx.x * blockDim.x + threadIdx.x;
    if (i == 0) g_total = 0;                     // seed for k_offsets
    if (i >= e) return;
    int d = s_is64 ? (int)((const long long*)ei)[e + i]
                   : ((const int*)ei)[e + i];
    if ((unsigned)d < (unsigned)n) atomicAdd(&g_cnt[d], 1);
}

// ---------------------------------------------------------------------------
// One-kernel CSR offsets: block-local scan + atomic block base. Also emits
// dinv = rsqrt(deg+1) and restores g_cnt to 0 for the next replay.
// ---------------------------------------------------------------------------
__global__ void k_offsets(int n) {
    __shared__ int sh[256];
    __shared__ int base;
    int i = blockIdx.x * 256 + threadIdx.x;
    int v = (i < n) ? g_cnt[i] : 0;
    sh[threadIdx.x] = v;
    __syncthreads();
    #pragma unroll
    for (int off = 1; off < 256; off <<= 1) {
        int t = (threadIdx.x >= off) ? sh[threadIdx.x - off] : 0;
        __syncthreads();
        sh[threadIdx.x] += t;
        __syncthreads();
    }
    if (threadIdx.x == 255) base = atomicAdd(&g_total, sh[255]);
    __syncthreads();
    if (i < n) {
        int o = base + sh[threadIdx.x] - v;   // exclusive within block + base
        g_off[i] = o;
        g_cursor[i] = o;
        g_dinv[i] = rsqrtf((float)v + 1.0f);
        g_cnt[i] = 0;                         // restore for next replay
    }
}

// Fill CSR straight off the input buffer: g_esrc[pos] = src, grouped by dst.
__global__ void k_fill(const void* __restrict__ ei, int e, int n) {
    __shared__ int s_is64;
    if (threadIdx.x < 32) {
        int v = ((const int*)ei)[1 + 2 * threadIdx.x];
        unsigned nz = __ballot_sync(0xFFFFFFFFu, v != 0);
        if (threadIdx.x == 0) s_is64 = (nz == 0) ? 1 : 0;
    }
    __syncthreads();
    int i = blockIdx.x * blockDim.x + threadIdx.x;
    if (i >= e) return;
    int s, d;
    if (s_is64) {
        const long long* p = (const long long*)ei;
        s = (int)p[i];
        d = (int)p[e + i];
    } else {
        const int* p = (const int*)ei;
        s = p[i];
        d = p[e + i];
    }
    if ((unsigned)d >= (unsigned)n) return;
    if ((unsigned)s >= (unsigned)n) s = 0;
    int pos = atomicAdd(&g_cursor[d], 1);
    g_esrc[pos] = s;
}

// ---------------------------------------------------------------------------
// One-time W split: W[k][n] fp32 -> bf16 hi/lo planes (row-major [k][n]).
// ---------------------------------------------------------------------------
__global__ void k_wsplit(const float* __restrict__ W) {
    int i = blockIdx.x * blockDim.x + threadIdx.x;   // < 16384
    float v = W[i];
    __nv_bfloat16 h = __float2bfloat16(v);
    __nv_bfloat16 l = __float2bfloat16(v - __bfloat162float(h));
    ((__nv_bfloat16*)g_Whi4)[i] = h;
    ((__nv_bfloat16*)g_Wlo4)[i] = l;
}

// ---------------------------------------------------------------------------
// HMMA GEMM: y = x @ W (UNscaled) via bf16 hi/lo 3-term split; fp32 accum,
// result stored as fp16. M=64 tiles -> 104 KB smem -> 2 CTAs/SM (16 warps)
// for latency hiding. 8 warps = 4 row-groups x 2 N-halves; per-output
// k-accumulation order is identical to the M=128 version (bitwise-same y).
// ---------------------------------------------------------------------------
#define SM_A_HI 0
#define SM_A_LO (SM_A_HI + 64 * LDA * 2)      // 17408
#define SM_B_HI (SM_A_LO + 64 * LDA * 2)      // 34816
#define SM_B_LO (SM_B_HI + 128 * LDA * 2)     // 69632
#define SMEM_TOTAL (SM_B_LO + 128 * LDA * 2)  // 104448

__global__ void __launch_bounds__(GEMM_THREADS, 2)
k_gemm_mma(const float* __restrict__ x, int n) {
    extern __shared__ __align__(16) char smem[];
    const uint32_t smem_base = smem_u32(smem);
    const int tid  = threadIdx.x;
    const int w    = tid >> 5;
    const int lane = tid & 31;
    const int row0 = blockIdx.x * TILE_M;

    // --- Copy precomputed W planes into padded SMEM (uint4 = 8 bf16) ---
    #pragma unroll 4
    for (int i = tid; i < 2048; i += GEMM_THREADS) {
        int r  = i >> 4;
        int c8 = (i & 15) * 8;
        size_t o = (size_t)(r * LDA + c8) * 2;
        *(uint4*)(smem + SM_B_HI + o) = g_Whi4[i];
        *(uint4*)(smem + SM_B_LO + o) = g_Wlo4[i];
    }

    // --- Convert x tile (64 rows) -> As_hi/As_lo (row-major [m][k], padded) ---
    #pragma unroll 4
    for (int i = tid; i < 64 * 32; i += GEMM_THREADS) {
        int r  = i >> 5;
        int c4 = (i & 31) * 4;
        int row = row0 + r;
        if (row >= n) row = n - 1;
        float4 v = *(const float4*)&x[(size_t)row * D + c4];
        __nv_bfloat16 hx = __float2bfloat16(v.x), hy = __float2bfloat16(v.y);
        __nv_bfloat16 hz = __float2bfloat16(v.z), hw = __float2bfloat16(v.w);
        __nv_bfloat16 lx = __float2bfloat16(v.x - __bfloat162float(hx));
        __nv_bfloat16 ly = __float2bfloat16(v.y - __bfloat162float(hy));
        __nv_bfloat16 lz = __float2bfloat16(v.z - __bfloat162float(hz));
        __nv_bfloat16 lw = __float2bfloat16(v.w - __bfloat162float(hw));
        size_t o = (size_t)(r * LDA + c4) * 2;
        *(__nv_bfloat162*)(smem + SM_A_HI + o)     = __nv_bfloat162(hx, hy);
        *(__nv_bfloat162*)(smem + SM_A_HI + o + 4) = __nv_bfloat162(hz, hw);
        *(__nv_bfloat162*)(smem + SM_A_LO + o)     = __nv_bfloat162(lx, ly);
        *(__nv_bfloat162*)(smem + SM_A_LO + o + 4) = __nv_bfloat162(lz, lw);
    }
    __syncthreads();

    float acc[8][4];
    #pragma unroll
    for (int t = 0; t < 8; t++)
        acc[t][0] = acc[t][1] = acc[t][2] = acc[t][3] = 0.0f;

    const int mw    = w & 3;        // row group (rows mw*16 .. mw*16+15)
    const int nhalf = w >> 2;       // N half: cols nhalf*64 .. nhalf*64+63
    const int m0 = mw * 16;
    const int amat = lane >> 3;
    const int arow = m0 + ((amat & 1) * 8) + (lane & 7);
    const int acol8 = (amat >> 1) * 8;
    const int bmat = (lane >> 3) & 1;
    const int brow_base = bmat * 8 + (lane & 7);

    #pragma unroll
    for (int ks = 0; ks < 8; ks++) {
        uint32_t a_hi[4], a_lo[4];
        uint32_t a_addr = smem_base + SM_A_HI +
                          (uint32_t)(arow * LDA + ks * 16 + acol8) * 2;
        ldsm_x4(a_hi[0], a_hi[1], a_hi[2], a_hi[3], a_addr);
        ldsm_x4(a_lo[0], a_lo[1], a_lo[2], a_lo[3],
                a_addr + (SM_A_LO - SM_A_HI));

        uint32_t b_base = smem_base + SM_B_HI +
                          (uint32_t)((ks * 16 + brow_base) * LDA + nhalf * 64) * 2;
        #pragma unroll
        for (int nt = 0; nt < 8; nt++) {
            uint32_t b_hi[2], b_lo[2];
            uint32_t b_addr = b_base + nt * 16;
            ldsm_x2_trans(b_hi[0], b_hi[1], b_addr);
            ldsm_x2_trans(b_lo[0], b_lo[1], b_addr + (SM_B_LO - SM_B_HI));
            mma_bf16(acc[nt], a_hi, b_hi);
            mma_bf16(acc[nt], a_hi, b_lo);
            mma_bf16(acc[nt], a_lo, b_hi);
        }
    }

    // --- Epilogue: write raw y as fp16 (no scaling — dinv applied in gather) ---
    const int r_lo  = lane >> 2;
    const int cpair = (lane & 3) * 2;
    const int row_a = row0 + m0 + r_lo;
    const int row_b = row_a + 8;

    #pragma unroll
    for (int nt = 0; nt < 8; nt++) {
        int col = nhalf * 64 + nt * 8 + cpair;
        if (row_a < n) {
            *(__half2*)&g_yh[(size_t)row_a * D + col] =
                __floats2half2_rn(acc[nt][0], acc[nt][1]);
        }
        if (row_b < n) {
            *(__half2*)&g_yh[(size_t)row_b * D + col] =
                __floats2half2_rn(acc[nt][2], acc[nt][3]);
        }
    }
}

// ---------------------------------------------------------------------------
// Gather (round-15 version — proven best): one warp per destination. Lanes
// batch-load up to 32 src ids (coalesced), shfl-broadcast them, accumulate
// dinv[s]-weighted columns in fp32 registers from fp16 y rows (8B per lane).
// out[d] = dd*(dd*y[d] + sum dinv[s]*y[s]) + b.
// ---------------------------------------------------------------------------
__global__ void __launch_bounds__(256) k_gather(const float* __restrict__ b,
                                                float* __restrict__ out,
                                                int n) {
    int d = (blockIdx.x * 256 + threadIdx.x) >> 5;
    if (d >= n) return;
    int lane = threadIdx.x & 31;
    const __half* __restrict__ y = g_yh;

    int beg = g_off[d];
    int cnt = g_cursor[d] - beg;     // filled count
    float dd = g_dinv[d];

    uint2 uself = *(const uint2*)(y + (size_t)d * D + lane * 4);
    float2 s0 = __half22float2(*(__half2*)&uself.x);
    float2 s1 = __half22float2(*(__half2*)&uself.y);
    float4 acc;                      // self-loop term: dd * y[d]
    acc.x = dd * s0.x; acc.y = dd * s0.y; acc.z = dd * s1.x; acc.w = dd * s1.y;

    int k = 0;
    while (k < cnt) {
        int m = cnt - k;
        if (m > 32) m = 32;
        int s = (lane < m) ? g_esrc[beg + k + lane] : 0;
        for (int j = 0; j < m; j++) {
            int sj = __shfl_sync(0xFFFFFFFFu, s, j);
            float ds = g_dinv[sj];
            uint2 u = *(const uint2*)(y + (size_t)sj * D + lane * 4);
            float2 f0 = __half22float2(*(__half2*)&u.x);
            float2 f1 = __half22float2(*(__half2*)&u.y);
            acc.x = fmaf(ds, f0.x, acc.x);
            acc.y = fmaf(ds, f0.y, acc.y);
            acc.z = fmaf(ds, f1.x, acc.z);
            acc.w = fmaf(ds, f1.y, acc.w);
        }
        k += m;
    }

    float4 bb = *(const float4*)&b[lane * 4];
    float4 r;
    r.x = fmaf(acc.x, dd, bb.x);
    r.y = fmaf(acc.y, dd, bb.y);
    r.z = fmaf(acc.z, dd, bb.z);
    r.w = fmaf(acc.w, dd, bb.w);
    *(float4*)&out[(size_t)d * D + lane * 4] = r;
}

// ---------------------------------------------------------------------------
extern "C" void kernel_launch(void* const* d_in, const int* in_sizes, int n_in,
                              void* d_out, int out_size) {
    const float* x  = (const float*)d_in[0];
    const void*  ei = (const void*)d_in[1];
    const float* W  = (const float*)d_in[2];
    const float* b  = (const float*)d_in[3];
    float* out = (float*)d_out;

    int n = in_sizes[0] / D;   // 100000
    int e = in_sizes[1] / 2;   // 600000
    int nb = (n + 255) / 256;  // 391

    // Fork the GEMM pipeline (wsplit -> gemm, depends only on x/W) onto a
    // side stream so it overlaps the edge pipeline; join before the gather.
    cudaStream_t s2;
    cudaStreamCreateWithFlags(&s2, cudaStreamNonBlocking);
    cudaEvent_t e_fork, e_gemm;
    cudaEventCreateWithFlags(&e_fork, cudaEventDisableTiming);
    cudaEventCreateWithFlags(&e_gemm, cudaEventDisableTiming);

    cudaEventRecord(e_fork, 0);
    cudaStreamWaitEvent(s2, e_fork, 0);

    // Stream B: GEMM pipeline
    k_wsplit<<<64, 256, 0, s2>>>(W);
    cudaFuncSetAttribute(k_gemm_mma, cudaFuncAttributeMaxDynamicSharedMemorySize,
                         SMEM_TOTAL);
    k_gemm_mma<<<(n + TILE_M - 1) / TILE_M, GEMM_THREADS, SMEM_TOTAL, s2>>>(x, n);
    cudaEventRecord(e_gemm, s2);

    // Stream A (capture stream): edge pipeline
    k_hist<<<(e + 255) / 256, 256>>>(ei, e, n);
    k_offsets<<<nb, 256>>>(n);
    k_fill<<<(e + 255) / 256, 256>>>(ei, e, n);

    // Join and gather
    cudaStreamWaitEvent(0, e_gemm, 0);
    k_gather<<<(n * 32 + 255) / 256, 256>>>(b, out, n);
}